// round 14
// baseline (speedup 1.0000x reference)
#include <cuda_runtime.h>
#include <cuda_bf16.h>
#include <cuda_fp16.h>
#include <math.h>

#define N_ENT  50000
#define N_REL  16
#define N_EDGE 1000000
#define DOUT_TOTAL 176

// ---------------- scratch ----------------
__device__ __half g_projh[(size_t)N_REL * N_ENT * 64];  // 102.4 MB (fp16)
__device__ float g_att[N_EDGE];     // attention logits, CSR(dst)-sorted order
__device__ float g_a[N_EDGE];       // softmax-normalized coefs, CSR order
__device__ int   g_deg[N_ENT];
__device__ int   g_incl[N_ENT];
__device__ int   g_offs[N_ENT + 1];
__device__ int   g_cursor[N_ENT];
__device__ int   g_bsum[256];
__device__ int   g_srcs[N_EDGE];    // src, CSR order
__device__ int   g_dsts[N_EDGE];    // dst, CSR order
__device__ int   g_ets[N_EDGE];     // etype, CSR order
__device__ float g_h1[(size_t)N_ENT * 64];
__device__ float g_h2[(size_t)N_ENT * 32];

// packed fp32x2 FMA (Blackwell dual-fp32 pipe)
__device__ __forceinline__ float2 ffma2(float2 a, float2 b, float2 c) {
    float2 d;
    asm("fma.rn.f32x2 %0, %1, %2, %3;"
        : "=l"(reinterpret_cast<unsigned long long&>(d))
        : "l"(reinterpret_cast<const unsigned long long&>(a)),
          "l"(reinterpret_cast<const unsigned long long&>(b)),
          "l"(reinterpret_cast<const unsigned long long&>(c)));
    return d;
}

__device__ __forceinline__ unsigned f2tf32(float f) {
    unsigned u;
    asm("cvt.rna.tf32.f32 %0, %1;" : "=r"(u) : "f"(f));
    return u;
}

__device__ __forceinline__ float tanha(float x) {
    float y;
    asm("tanh.approx.f32 %0, %1;" : "=f"(y) : "f"(x));
    return y;
}

__device__ __forceinline__ void mma_tf32(float& d0, float& d1, float& d2, float& d3,
                                         unsigned a0, unsigned a1, unsigned a2, unsigned a3,
                                         unsigned b0, unsigned b1) {
    asm("mma.sync.aligned.m16n8k8.row.col.f32.tf32.tf32.f32 "
        "{%0,%1,%2,%3}, {%4,%5,%6,%7}, {%8,%9}, {%0,%1,%2,%3};"
        : "+f"(d0), "+f"(d1), "+f"(d2), "+f"(d3)
        : "r"(a0), "r"(a1), "r"(a2), "r"(a3), "r"(b0), "r"(b1));
}

// ---------------- init ----------------
__global__ __launch_bounds__(256) void k_zero() {
    int i = blockIdx.x * blockDim.x + threadIdx.x;
    if (i < N_ENT) { g_deg[i] = 0; g_cursor[i] = 0; }
}

// ---------------- proj[r,n,e] = sum_d ent[n,d] * W_R[r,d,e]  (tensor cores, fp16 out) ------
// Block: 256 thr (8 warps). Tile: 64 nodes x 64 cols, 8 relations per block.
// Warp: 32 nodes x 16 cols. mt loop innermost -> 2 interleaved mma chains (ILP 2).
__global__ __launch_bounds__(256, 2) void k_proj(const float* __restrict__ ent,
                                                 const float* __restrict__ WR) {
    __shared__ unsigned entS[64 * 68];   // [node][k], pitch 68 -> conflict-free frags
    __shared__ unsigned WT[64 * 68];     // [n][k] transposed, pitch 68

    const int tid  = threadIdx.x;
    const int lane = tid & 31;
    const int w    = tid >> 5;
    const int n0   = blockIdx.x * 64;

    // fill entS (tf32-converted)
    for (int i = tid; i < 1024; i += 256) {
        int row = i >> 4, q = i & 15;
        int n = n0 + row;
        float4 v = (n < N_ENT)
            ? reinterpret_cast<const float4*>(ent + (size_t)n * 64)[q]
            : make_float4(0.f, 0.f, 0.f, 0.f);
        entS[row * 68 + 4 * q + 0] = f2tf32(v.x);
        entS[row * 68 + 4 * q + 1] = f2tf32(v.y);
        entS[row * 68 + 4 * q + 2] = f2tf32(v.z);
        entS[row * 68 + 4 * q + 3] = f2tf32(v.w);
    }
    __syncthreads();

    const int grp  = lane >> 2;       // 0..7
    const int tq   = lane & 3;        // 0..3
    const int mb   = (w >> 2) * 32;   // node base within tile (0 or 32)
    const int nb   = (w & 3) * 16;    // col base within tile (0,16,32,48)

    // cache A fragments (2 m-tiles x 8 k-tiles), reused for all 8 relations
    unsigned a[2][8][4];
#pragma unroll
    for (int mt = 0; mt < 2; mt++) {
        int rowA = mb + mt * 16 + grp;
#pragma unroll
        for (int kt = 0; kt < 8; kt++) {
            int col = kt * 8 + tq;
            a[mt][kt][0] = entS[rowA * 68 + col];
            a[mt][kt][1] = entS[(rowA + 8) * 68 + col];
            a[mt][kt][2] = entS[rowA * 68 + col + 4];
            a[mt][kt][3] = entS[(rowA + 8) * 68 + col + 4];
        }
    }

    for (int rr = 0; rr < 8; rr++) {
        const int r = blockIdx.y * 8 + rr;
        __syncthreads();   // protect WT from previous iteration's reads
        const float* W = WR + (size_t)r * 4096;
        for (int i = tid; i < 4096; i += 256) {
            int k = i >> 6, n = i & 63;
            WT[n * 68 + k] = f2tf32(W[i]);
        }
        __syncthreads();

        __half* outb = g_projh + ((size_t)r * N_ENT + n0) * 64;
#pragma unroll
        for (int nt = 0; nt < 2; nt++) {
            unsigned b[8][2];
            const unsigned* wb = &WT[(nb + nt * 8 + grp) * 68];
#pragma unroll
            for (int kt = 0; kt < 8; kt++) {
                b[kt][0] = wb[kt * 8 + tq];
                b[kt][1] = wb[kt * 8 + tq + 4];
            }
            float d[2][4];
#pragma unroll
            for (int mt = 0; mt < 2; mt++)
                d[mt][0] = d[mt][1] = d[mt][2] = d[mt][3] = 0.f;
            // kt outer, mt inner: two independent mma chains interleave (ILP 2)
#pragma unroll
            for (int kt = 0; kt < 8; kt++) {
#pragma unroll
                for (int mt = 0; mt < 2; mt++)
                    mma_tf32(d[mt][0], d[mt][1], d[mt][2], d[mt][3],
                             a[mt][kt][0], a[mt][kt][1], a[mt][kt][2], a[mt][kt][3],
                             b[kt][0], b[kt][1]);
            }
            int colb = nb + nt * 8 + 2 * tq;
#pragma unroll
            for (int mt = 0; mt < 2; mt++) {
                int node0 = mb + mt * 16 + grp;
                int node1 = node0 + 8;
                if (n0 + node0 < N_ENT)
                    *reinterpret_cast<__half2*>(&outb[(size_t)node0 * 64 + colb]) =
                        __floats2half2_rn(d[mt][0], d[mt][1]);
                if (n0 + node1 < N_ENT)
                    *reinterpret_cast<__half2*>(&outb[(size_t)node1 * 64 + colb]) =
                        __floats2half2_rn(d[mt][2], d[mt][3]);
            }
        }
    }
}

// ---------------- CSR build ----------------
__global__ __launch_bounds__(256) void k_count(const int* __restrict__ dst) {
    int e = blockIdx.x * blockDim.x + threadIdx.x;
    if (e < N_EDGE) atomicAdd(&g_deg[dst[e]], 1);
}

__global__ __launch_bounds__(512) void k_scan1() {
    __shared__ int sm[512];
    int i = blockIdx.x * 512 + threadIdx.x;
    int v = (i < N_ENT) ? g_deg[i] : 0;
    sm[threadIdx.x] = v;
    __syncthreads();
    for (int off = 1; off < 512; off <<= 1) {
        int t = (threadIdx.x >= off) ? sm[threadIdx.x - off] : 0;
        __syncthreads();
        sm[threadIdx.x] += t;
        __syncthreads();
    }
    if (i < N_ENT) g_incl[i] = sm[threadIdx.x];
    if (threadIdx.x == 511) g_bsum[blockIdx.x] = sm[511];
}

__global__ void k_scan2(int nb) {
    if (blockIdx.x == 0 && threadIdx.x == 0) {
        int run = 0;
        for (int b = 0; b < nb; b++) { int t = g_bsum[b]; g_bsum[b] = run; run += t; }
    }
}

__global__ __launch_bounds__(512) void k_scan3() {
    int i = blockIdx.x * blockDim.x + threadIdx.x;
    if (i < N_ENT) g_offs[i] = g_incl[i] - g_deg[i] + g_bsum[i / 512];
    if (i == 0) g_offs[N_ENT] = N_EDGE;
}

__global__ __launch_bounds__(256) void k_scatter(const int* __restrict__ src,
                                                 const int* __restrict__ dst,
                                                 const int* __restrict__ et) {
    int e = blockIdx.x * blockDim.x + threadIdx.x;
    if (e < N_EDGE) {
        int d = dst[e];
        int pos = g_offs[d] + atomicAdd(&g_cursor[d], 1);
        g_srcs[pos] = src[e];
        g_dsts[pos] = d;
        g_ets[pos]  = et[e];
    }
}

// ---------------- attention logits: 8 lanes per edge, 4 edges per warp ----------------
// fp16 proj row = 128B = 8 lanes x LDG.128; tanh.approx on MUFU; 3-shfl reduce.
__global__ __launch_bounds__(256) void k_att(const float* __restrict__ rel) {
    int w = (blockIdx.x * blockDim.x + threadIdx.x) >> 5;
    int lane = threadIdx.x & 31;
    int base = w * 4;                 // N_EDGE % 4 == 0
    if (base >= N_EDGE) return;

    int g   = lane >> 3;              // edge slot 0..3
    int sub = lane & 7;               // 16B chunk within row

    int mv = 0;
    int el = base + (lane & 3);
    if (lane < 4)                      mv = g_srcs[el];
    else if (lane >= 8 && lane < 12)   mv = g_dsts[el];
    else if (lane >= 16 && lane < 20)  mv = g_ets[el];

    int s = __shfl_sync(0xffffffffu, mv, g);
    int d = __shfl_sync(0xffffffffu, mv, 8 + g);
    int r = __shfl_sync(0xffffffffu, mv, 16 + g);

    const uint4* pt = reinterpret_cast<const uint4*>(g_projh + ((size_t)r * N_ENT + s) * 64);
    const uint4* ph = reinterpret_cast<const uint4*>(g_projh + ((size_t)r * N_ENT + d) * 64);
    uint4 tv = pt[sub];
    uint4 hv = ph[sub];
    const float4* pr = reinterpret_cast<const float4*>(rel + (size_t)r * 64);
    float4 r0 = pr[2 * sub], r1 = pr[2 * sub + 1];

    const __half2* t2p = reinterpret_cast<const __half2*>(&tv);
    const __half2* h2p = reinterpret_cast<const __half2*>(&hv);
    float rc[8] = {r0.x, r0.y, r0.z, r0.w, r1.x, r1.y, r1.z, r1.w};

    float p = 0.0f;
#pragma unroll
    for (int q = 0; q < 4; q++) {
        float2 t2 = __half22float2(t2p[q]);
        float2 h2 = __half22float2(h2p[q]);
        p += t2.x * tanha(h2.x + rc[2 * q]);
        p += t2.y * tanha(h2.y + rc[2 * q + 1]);
    }
    // reduce within 8-lane group
    p += __shfl_xor_sync(0xffffffffu, p, 1);
    p += __shfl_xor_sync(0xffffffffu, p, 2);
    p += __shfl_xor_sync(0xffffffffu, p, 4);
    if (sub == 0) g_att[base + g] = p;
}

// ---------------- edge softmax by dst (warp per node, all-sequential IO) ----------------
__global__ __launch_bounds__(256) void k_softmax() {
    int n = blockIdx.x * (blockDim.x >> 5) + (threadIdx.x >> 5);
    int lane = threadIdx.x & 31;
    if (n >= N_ENT) return;
    int beg = g_offs[n], end = g_offs[n + 1];
    if (beg == end) return;
    float m = -3.4e38f;
    for (int p = beg + lane; p < end; p += 32) m = fmaxf(m, g_att[p]);
#pragma unroll
    for (int o = 16; o; o >>= 1) m = fmaxf(m, __shfl_xor_sync(0xffffffffu, m, o));
    float s = 0.0f;
    for (int p = beg + lane; p < end; p += 32) {
        float e = expf(g_att[p] - m);
        g_a[p] = e;
        s += e;
    }
#pragma unroll
    for (int o = 16; o; o >>= 1) s += __shfl_xor_sync(0xffffffffu, s, o);
    float inv = 1.0f / s;
    for (int p = beg + lane; p < end; p += 32) g_a[p] *= inv;
}

// ---------------- fused layer: agg + bi-interaction + l2norm + output ----------------
template <int L>
__global__ __launch_bounds__(256) void k_layer(const float* __restrict__ ent,
                                               const float* __restrict__ W1,
                                               const float* __restrict__ b1,
                                               const float* __restrict__ W2,
                                               const float* __restrict__ b2,
                                               float* __restrict__ out) {
    constexpr int DIN  = (L == 0) ? 64 : (L == 1) ? 64 : 32;
    constexpr int DOUT = (L == 0) ? 64 : (L == 1) ? 32 : 16;
    constexpr int CB   = (L == 0) ? 64 : (L == 1) ? 128 : 160;
    constexpr int V    = DIN / 32;
    constexpr int OV   = (DOUT + 31) / 32;
    const float* hin = (L == 0) ? ent : (L == 1) ? g_h1 : g_h2;
    float* hout      = (L == 0) ? g_h1 : (L == 1) ? g_h2 : nullptr;

    __shared__ float2 Wint[DIN * DOUT];
    __shared__ float2 bint[DOUT];
    for (int i = threadIdx.x; i < DIN * DOUT; i += blockDim.x)
        Wint[i] = make_float2(W1[i], W2[i]);
    if (threadIdx.x < DOUT)
        bint[threadIdx.x] = make_float2(b1[threadIdx.x], b2[threadIdx.x]);
    __syncthreads();

    int lane = threadIdx.x & 31;
    int n = blockIdx.x * (blockDim.x >> 5) + (threadIdx.x >> 5);
    if (n >= N_ENT) return;

    float hv[V], nv[V];
#pragma unroll
    for (int v = 0; v < V; v++) {
        hv[v] = hin[(size_t)n * DIN + lane + 32 * v];
        nv[v] = 0.0f;
    }
    int beg = g_offs[n], end = g_offs[n + 1];
    for (int p = beg; p < end; p++) {
        float c = g_a[p];
        const float* hs = hin + (size_t)g_srcs[p] * DIN;
#pragma unroll
        for (int v = 0; v < V; v++) nv[v] += c * hs[lane + 32 * v];
    }

    float sv1[V], sv2[V];
#pragma unroll
    for (int v = 0; v < V; v++) { sv1[v] = hv[v] + nv[v]; sv2[v] = hv[v] * nv[v]; }

    float2 acc[OV];
#pragma unroll
    for (int o = 0; o < OV; o++) acc[o] = make_float2(0.0f, 0.0f);
#pragma unroll
    for (int i = 0; i < DIN; i++) {
        float x1 = __shfl_sync(0xffffffffu, sv1[i >> 5], i & 31);
        float x2 = __shfl_sync(0xffffffffu, sv2[i >> 5], i & 31);
        float2 xp = make_float2(x1, x2);
#pragma unroll
        for (int o = 0; o < OV; o++) {
            int j = lane + 32 * o;
            if (j < DOUT) acc[o] = ffma2(xp, Wint[i * DOUT + j], acc[o]);
        }
    }

    float y[OV];
    float ss = 0.0f;
#pragma unroll
    for (int o = 0; o < OV; o++) {
        int j = lane + 32 * o;
        if (j < DOUT) {
            float y1 = acc[o].x + bint[j].x; y1 = (y1 > 0.0f) ? y1 : 0.01f * y1;
            float y2 = acc[o].y + bint[j].y; y2 = (y2 > 0.0f) ? y2 : 0.01f * y2;
            y[o] = y1 + y2;
            ss += y[o] * y[o];
        }
    }
#pragma unroll
    for (int o = 16; o; o >>= 1) ss += __shfl_xor_sync(0xffffffffu, ss, o);
    float inv = 1.0f / fmaxf(sqrtf(ss), 1e-12f);

#pragma unroll
    for (int o = 0; o < OV; o++) {
        int j = lane + 32 * o;
        if (j < DOUT) {
            if (hout) hout[(size_t)n * DOUT + j] = y[o];
            out[(size_t)n * DOUT_TOTAL + CB + j] = y[o] * inv;
        }
    }
    if (L == 0) {
#pragma unroll
        for (int v = 0; v < V; v++)
            out[(size_t)n * DOUT_TOTAL + lane + 32 * v] = hv[v];
    }
}

// ---------------- launch ----------------
extern "C" void kernel_launch(void* const* d_in, const int* in_sizes, int n_in,
                              void* d_out, int out_size) {
    const float* ent  = (const float*)d_in[0];
    const float* rel  = (const float*)d_in[1];
    const float* WR   = (const float*)d_in[2];
    const float* W1_0 = (const float*)d_in[3];
    const float* b1_0 = (const float*)d_in[4];
    const float* W2_0 = (const float*)d_in[5];
    const float* b2_0 = (const float*)d_in[6];
    const float* W1_1 = (const float*)d_in[7];
    const float* b1_1 = (const float*)d_in[8];
    const float* W2_1 = (const float*)d_in[9];
    const float* b2_1 = (const float*)d_in[10];
    const float* W1_2 = (const float*)d_in[11];
    const float* b1_2 = (const float*)d_in[12];
    const float* W2_2 = (const float*)d_in[13];
    const float* b2_2 = (const float*)d_in[14];
    const int* src = (const int*)d_in[15];
    const int* dst = (const int*)d_in[16];
    const int* et  = (const int*)d_in[17];
    float* out = (float*)d_out;

    const int NB_SCAN = (N_ENT + 511) / 512;   // 98

    k_zero<<<(N_ENT + 255) / 256, 256>>>();
    k_count<<<(N_EDGE + 255) / 256, 256>>>(dst);
    k_scan1<<<NB_SCAN, 512>>>();
    k_proj<<<dim3((N_ENT + 63) / 64, N_REL / 8), 256>>>(ent, WR);
    k_scan2<<<1, 32>>>(NB_SCAN);
    k_scan3<<<(N_ENT + 511) / 512, 512>>>();
    k_scatter<<<(N_EDGE + 255) / 256, 256>>>(src, dst, et);
    k_att<<<(N_EDGE / 4 + 7) / 8, 256>>>(rel);
    k_softmax<<<(N_ENT + 7) / 8, 256>>>();
    k_layer<0><<<(N_ENT + 7) / 8, 256>>>(ent, W1_0, b1_0, W2_0, b2_0, out);
    k_layer<1><<<(N_ENT + 7) / 8, 256>>>(ent, W1_1, b1_1, W2_1, b2_1, out);
    k_layer<2><<<(N_ENT + 7) / 8, 256>>>(ent, W1_2, b1_2, W2_2, b2_2, out);
}

// round 15
// speedup vs baseline: 1.0007x; 1.0007x over previous
#include <cuda_runtime.h>
#include <cuda_bf16.h>
#include <cuda_fp16.h>
#include <math.h>

#define N_ENT  50000
#define N_REL  16
#define N_EDGE 1000000
#define DOUT_TOTAL 176

// ---------------- scratch ----------------
__device__ __half g_projh[(size_t)N_REL * N_ENT * 64];  // 102.4 MB (fp16)
__device__ float g_att[N_EDGE];     // attention logits, CSR(dst)-sorted order
__device__ float g_a[N_EDGE];       // softmax-normalized coefs, CSR order
__device__ int   g_deg[N_ENT];
__device__ int   g_incl[N_ENT];
__device__ int   g_offs[N_ENT + 1];
__device__ int   g_cursor[N_ENT];
__device__ int   g_bsum[256];
__device__ int   g_srcs[N_EDGE];    // src, CSR order
__device__ int   g_dsts[N_EDGE];    // dst, CSR order
__device__ int   g_ets[N_EDGE];     // etype, CSR order
__device__ float g_h1[(size_t)N_ENT * 64];
__device__ float g_h2[(size_t)N_ENT * 32];

// packed fp32x2 FMA (Blackwell dual-fp32 pipe)
__device__ __forceinline__ float2 ffma2(float2 a, float2 b, float2 c) {
    float2 d;
    asm("fma.rn.f32x2 %0, %1, %2, %3;"
        : "=l"(reinterpret_cast<unsigned long long&>(d))
        : "l"(reinterpret_cast<const unsigned long long&>(a)),
          "l"(reinterpret_cast<const unsigned long long&>(b)),
          "l"(reinterpret_cast<const unsigned long long&>(c)));
    return d;
}

__device__ __forceinline__ unsigned f2tf32(float f) {
    unsigned u;
    asm("cvt.rna.tf32.f32 %0, %1;" : "=r"(u) : "f"(f));
    return u;
}

__device__ __forceinline__ float tanha(float x) {
    float y;
    asm("tanh.approx.f32 %0, %1;" : "=f"(y) : "f"(x));
    return y;
}

__device__ __forceinline__ void mma_tf32(float& d0, float& d1, float& d2, float& d3,
                                         unsigned a0, unsigned a1, unsigned a2, unsigned a3,
                                         unsigned b0, unsigned b1) {
    asm("mma.sync.aligned.m16n8k8.row.col.f32.tf32.tf32.f32 "
        "{%0,%1,%2,%3}, {%4,%5,%6,%7}, {%8,%9}, {%0,%1,%2,%3};"
        : "+f"(d0), "+f"(d1), "+f"(d2), "+f"(d3)
        : "r"(a0), "r"(a1), "r"(a2), "r"(a3), "r"(b0), "r"(b1));
}

// ---------------- init ----------------
__global__ __launch_bounds__(256) void k_zero() {
    int i = blockIdx.x * blockDim.x + threadIdx.x;
    if (i < N_ENT) { g_deg[i] = 0; g_cursor[i] = 0; }
}

// ---------------- proj[r,n,e] = sum_d ent[n,d] * W_R[r,d,e]  (tensor cores, fp16 out) ------
// Block: 256 thr (8 warps). Tile: 64 nodes x 64 cols, 8 relations per block.
// Warp: 32 nodes x 16 cols. mt loop innermost -> 2 interleaved mma chains (ILP 2).
__global__ __launch_bounds__(256, 2) void k_proj(const float* __restrict__ ent,
                                                 const float* __restrict__ WR) {
    __shared__ unsigned entS[64 * 68];   // [node][k], pitch 68 -> conflict-free frags
    __shared__ unsigned WT[64 * 68];     // [n][k] transposed, pitch 68

    const int tid  = threadIdx.x;
    const int lane = tid & 31;
    const int w    = tid >> 5;
    const int n0   = blockIdx.x * 64;

    // fill entS (tf32-converted)
    for (int i = tid; i < 1024; i += 256) {
        int row = i >> 4, q = i & 15;
        int n = n0 + row;
        float4 v = (n < N_ENT)
            ? reinterpret_cast<const float4*>(ent + (size_t)n * 64)[q]
            : make_float4(0.f, 0.f, 0.f, 0.f);
        entS[row * 68 + 4 * q + 0] = f2tf32(v.x);
        entS[row * 68 + 4 * q + 1] = f2tf32(v.y);
        entS[row * 68 + 4 * q + 2] = f2tf32(v.z);
        entS[row * 68 + 4 * q + 3] = f2tf32(v.w);
    }
    __syncthreads();

    const int grp  = lane >> 2;       // 0..7
    const int tq   = lane & 3;        // 0..3
    const int mb   = (w >> 2) * 32;   // node base within tile (0 or 32)
    const int nb   = (w & 3) * 16;    // col base within tile (0,16,32,48)

    // cache A fragments (2 m-tiles x 8 k-tiles), reused for all 8 relations
    unsigned a[2][8][4];
#pragma unroll
    for (int mt = 0; mt < 2; mt++) {
        int rowA = mb + mt * 16 + grp;
#pragma unroll
        for (int kt = 0; kt < 8; kt++) {
            int col = kt * 8 + tq;
            a[mt][kt][0] = entS[rowA * 68 + col];
            a[mt][kt][1] = entS[(rowA + 8) * 68 + col];
            a[mt][kt][2] = entS[rowA * 68 + col + 4];
            a[mt][kt][3] = entS[(rowA + 8) * 68 + col + 4];
        }
    }

    for (int rr = 0; rr < 8; rr++) {
        const int r = blockIdx.y * 8 + rr;
        __syncthreads();   // protect WT from previous iteration's reads
        const float* W = WR + (size_t)r * 4096;
        for (int i = tid; i < 4096; i += 256) {
            int k = i >> 6, n = i & 63;
            WT[n * 68 + k] = f2tf32(W[i]);
        }
        __syncthreads();

        __half* outb = g_projh + ((size_t)r * N_ENT + n0) * 64;
#pragma unroll
        for (int nt = 0; nt < 2; nt++) {
            unsigned b[8][2];
            const unsigned* wb = &WT[(nb + nt * 8 + grp) * 68];
#pragma unroll
            for (int kt = 0; kt < 8; kt++) {
                b[kt][0] = wb[kt * 8 + tq];
                b[kt][1] = wb[kt * 8 + tq + 4];
            }
            float d[2][4];
#pragma unroll
            for (int mt = 0; mt < 2; mt++)
                d[mt][0] = d[mt][1] = d[mt][2] = d[mt][3] = 0.f;
            // kt outer, mt inner: two independent mma chains interleave (ILP 2)
#pragma unroll
            for (int kt = 0; kt < 8; kt++) {
#pragma unroll
                for (int mt = 0; mt < 2; mt++)
                    mma_tf32(d[mt][0], d[mt][1], d[mt][2], d[mt][3],
                             a[mt][kt][0], a[mt][kt][1], a[mt][kt][2], a[mt][kt][3],
                             b[kt][0], b[kt][1]);
            }
            int colb = nb + nt * 8 + 2 * tq;
#pragma unroll
            for (int mt = 0; mt < 2; mt++) {
                int node0 = mb + mt * 16 + grp;
                int node1 = node0 + 8;
                if (n0 + node0 < N_ENT)
                    *reinterpret_cast<__half2*>(&outb[(size_t)node0 * 64 + colb]) =
                        __floats2half2_rn(d[mt][0], d[mt][1]);
                if (n0 + node1 < N_ENT)
                    *reinterpret_cast<__half2*>(&outb[(size_t)node1 * 64 + colb]) =
                        __floats2half2_rn(d[mt][2], d[mt][3]);
            }
        }
    }
}

// ---------------- CSR build ----------------
__global__ __launch_bounds__(256) void k_count(const int* __restrict__ dst) {
    int e = blockIdx.x * blockDim.x + threadIdx.x;
    if (e < N_EDGE) atomicAdd(&g_deg[dst[e]], 1);
}

__global__ __launch_bounds__(512) void k_scan1() {
    __shared__ int sm[512];
    int i = blockIdx.x * 512 + threadIdx.x;
    int v = (i < N_ENT) ? g_deg[i] : 0;
    sm[threadIdx.x] = v;
    __syncthreads();
    for (int off = 1; off < 512; off <<= 1) {
        int t = (threadIdx.x >= off) ? sm[threadIdx.x - off] : 0;
        __syncthreads();
        sm[threadIdx.x] += t;
        __syncthreads();
    }
    if (i < N_ENT) g_incl[i] = sm[threadIdx.x];
    if (threadIdx.x == 511) g_bsum[blockIdx.x] = sm[511];
}

__global__ void k_scan2(int nb) {
    if (blockIdx.x == 0 && threadIdx.x == 0) {
        int run = 0;
        for (int b = 0; b < nb; b++) { int t = g_bsum[b]; g_bsum[b] = run; run += t; }
    }
}

__global__ __launch_bounds__(512) void k_scan3() {
    int i = blockIdx.x * blockDim.x + threadIdx.x;
    if (i < N_ENT) g_offs[i] = g_incl[i] - g_deg[i] + g_bsum[i / 512];
    if (i == 0) g_offs[N_ENT] = N_EDGE;
}

__global__ __launch_bounds__(256) void k_scatter(const int* __restrict__ src,
                                                 const int* __restrict__ dst,
                                                 const int* __restrict__ et) {
    int e = blockIdx.x * blockDim.x + threadIdx.x;
    if (e < N_EDGE) {
        int d = dst[e];
        int pos = g_offs[d] + atomicAdd(&g_cursor[d], 1);
        g_srcs[pos] = src[e];
        g_dsts[pos] = d;
        g_ets[pos]  = et[e];
    }
}

// ---------------- attention logits: 8 lanes per edge, 4 edges per warp ----------------
// fp16 proj row = 128B = 8 lanes x LDG.128; tanh.approx on MUFU; 3-shfl reduce.
__global__ __launch_bounds__(256) void k_att(const float* __restrict__ rel) {
    int w = (blockIdx.x * blockDim.x + threadIdx.x) >> 5;
    int lane = threadIdx.x & 31;
    int base = w * 4;                 // N_EDGE % 4 == 0
    if (base >= N_EDGE) return;

    int g   = lane >> 3;              // edge slot 0..3
    int sub = lane & 7;               // 16B chunk within row

    int mv = 0;
    int el = base + (lane & 3);
    if (lane < 4)                      mv = g_srcs[el];
    else if (lane >= 8 && lane < 12)   mv = g_dsts[el];
    else if (lane >= 16 && lane < 20)  mv = g_ets[el];

    int s = __shfl_sync(0xffffffffu, mv, g);
    int d = __shfl_sync(0xffffffffu, mv, 8 + g);
    int r = __shfl_sync(0xffffffffu, mv, 16 + g);

    const uint4* pt = reinterpret_cast<const uint4*>(g_projh + ((size_t)r * N_ENT + s) * 64);
    const uint4* ph = reinterpret_cast<const uint4*>(g_projh + ((size_t)r * N_ENT + d) * 64);
    uint4 tv = pt[sub];
    uint4 hv = ph[sub];
    const float4* pr = reinterpret_cast<const float4*>(rel + (size_t)r * 64);
    float4 r0 = pr[2 * sub], r1 = pr[2 * sub + 1];

    const __half2* t2p = reinterpret_cast<const __half2*>(&tv);
    const __half2* h2p = reinterpret_cast<const __half2*>(&hv);
    float rc[8] = {r0.x, r0.y, r0.z, r0.w, r1.x, r1.y, r1.z, r1.w};

    float p = 0.0f;
#pragma unroll
    for (int q = 0; q < 4; q++) {
        float2 t2 = __half22float2(t2p[q]);
        float2 h2 = __half22float2(h2p[q]);
        p += t2.x * tanha(h2.x + rc[2 * q]);
        p += t2.y * tanha(h2.y + rc[2 * q + 1]);
    }
    // reduce within 8-lane group
    p += __shfl_xor_sync(0xffffffffu, p, 1);
    p += __shfl_xor_sync(0xffffffffu, p, 2);
    p += __shfl_xor_sync(0xffffffffu, p, 4);
    if (sub == 0) g_att[base + g] = p;
}

// ---------------- edge softmax by dst (warp per node, all-sequential IO) ----------------
__global__ __launch_bounds__(256) void k_softmax() {
    int n = blockIdx.x * (blockDim.x >> 5) + (threadIdx.x >> 5);
    int lane = threadIdx.x & 31;
    if (n >= N_ENT) return;
    int beg = g_offs[n], end = g_offs[n + 1];
    if (beg == end) return;
    float m = -3.4e38f;
    for (int p = beg + lane; p < end; p += 32) m = fmaxf(m, g_att[p]);
#pragma unroll
    for (int o = 16; o; o >>= 1) m = fmaxf(m, __shfl_xor_sync(0xffffffffu, m, o));
    float s = 0.0f;
    for (int p = beg + lane; p < end; p += 32) {
        float e = expf(g_att[p] - m);
        g_a[p] = e;
        s += e;
    }
#pragma unroll
    for (int o = 16; o; o >>= 1) s += __shfl_xor_sync(0xffffffffu, s, o);
    float inv = 1.0f / s;
    for (int p = beg + lane; p < end; p += 32) g_a[p] *= inv;
}

// ---------------- fused layer: agg + bi-interaction + l2norm + output ----------------
template <int L>
__global__ __launch_bounds__(256) void k_layer(const float* __restrict__ ent,
                                               const float* __restrict__ W1,
                                               const float* __restrict__ b1,
                                               const float* __restrict__ W2,
                                               const float* __restrict__ b2,
                                               float* __restrict__ out) {
    constexpr int DIN  = (L == 0) ? 64 : (L == 1) ? 64 : 32;
    constexpr int DOUT = (L == 0) ? 64 : (L == 1) ? 32 : 16;
    constexpr int CB   = (L == 0) ? 64 : (L == 1) ? 128 : 160;
    constexpr int V    = DIN / 32;
    constexpr int OV   = (DOUT + 31) / 32;
    const float* hin = (L == 0) ? ent : (L == 1) ? g_h1 : g_h2;
    float* hout      = (L == 0) ? g_h1 : (L == 1) ? g_h2 : nullptr;

    __shared__ float2 Wint[DIN * DOUT];
    __shared__ float2 bint[DOUT];
    for (int i = threadIdx.x; i < DIN * DOUT; i += blockDim.x)
        Wint[i] = make_float2(W1[i], W2[i]);
    if (threadIdx.x < DOUT)
        bint[threadIdx.x] = make_float2(b1[threadIdx.x], b2[threadIdx.x]);
    __syncthreads();

    int lane = threadIdx.x & 31;
    int n = blockIdx.x * (blockDim.x >> 5) + (threadIdx.x >> 5);
    if (n >= N_ENT) return;

    float hv[V], nv[V];
#pragma unroll
    for (int v = 0; v < V; v++) {
        hv[v] = hin[(size_t)n * DIN + lane + 32 * v];
        nv[v] = 0.0f;
    }
    int beg = g_offs[n], end = g_offs[n + 1];
    for (int p = beg; p < end; p++) {
        float c = g_a[p];
        const float* hs = hin + (size_t)g_srcs[p] * DIN;
#pragma unroll
        for (int v = 0; v < V; v++) nv[v] += c * hs[lane + 32 * v];
    }

    float sv1[V], sv2[V];
#pragma unroll
    for (int v = 0; v < V; v++) { sv1[v] = hv[v] + nv[v]; sv2[v] = hv[v] * nv[v]; }

    float2 acc[OV];
#pragma unroll
    for (int o = 0; o < OV; o++) acc[o] = make_float2(0.0f, 0.0f);
#pragma unroll
    for (int i = 0; i < DIN; i++) {
        float x1 = __shfl_sync(0xffffffffu, sv1[i >> 5], i & 31);
        float x2 = __shfl_sync(0xffffffffu, sv2[i >> 5], i & 31);
        float2 xp = make_float2(x1, x2);
#pragma unroll
        for (int o = 0; o < OV; o++) {
            int j = lane + 32 * o;
            if (j < DOUT) acc[o] = ffma2(xp, Wint[i * DOUT + j], acc[o]);
        }
    }

    float y[OV];
    float ss = 0.0f;
#pragma unroll
    for (int o = 0; o < OV; o++) {
        int j = lane + 32 * o;
        if (j < DOUT) {
            float y1 = acc[o].x + bint[j].x; y1 = (y1 > 0.0f) ? y1 : 0.01f * y1;
            float y2 = acc[o].y + bint[j].y; y2 = (y2 > 0.0f) ? y2 : 0.01f * y2;
            y[o] = y1 + y2;
            ss += y[o] * y[o];
        }
    }
#pragma unroll
    for (int o = 16; o; o >>= 1) ss += __shfl_xor_sync(0xffffffffu, ss, o);
    float inv = 1.0f / fmaxf(sqrtf(ss), 1e-12f);

#pragma unroll
    for (int o = 0; o < OV; o++) {
        int j = lane + 32 * o;
        if (j < DOUT) {
            if (hout) hout[(size_t)n * DOUT + j] = y[o];
            out[(size_t)n * DOUT_TOTAL + CB + j] = y[o] * inv;
        }
    }
    if (L == 0) {
#pragma unroll
        for (int v = 0; v < V; v++)
            out[(size_t)n * DOUT_TOTAL + lane + 32 * v] = hv[v];
    }
}

// ---------------- launch ----------------
extern "C" void kernel_launch(void* const* d_in, const int* in_sizes, int n_in,
                              void* d_out, int out_size) {
    const float* ent  = (const float*)d_in[0];
    const float* rel  = (const float*)d_in[1];
    const float* WR   = (const float*)d_in[2];
    const float* W1_0 = (const float*)d_in[3];
    const float* b1_0 = (const float*)d_in[4];
    const float* W2_0 = (const float*)d_in[5];
    const float* b2_0 = (const float*)d_in[6];
    const float* W1_1 = (const float*)d_in[7];
    const float* b1_1 = (const float*)d_in[8];
    const float* W2_1 = (const float*)d_in[9];
    const float* b2_1 = (const float*)d_in[10];
    const float* W1_2 = (const float*)d_in[11];
    const float* b1_2 = (const float*)d_in[12];
    const float* W2_2 = (const float*)d_in[13];
    const float* b2_2 = (const float*)d_in[14];
    const int* src = (const int*)d_in[15];
    const int* dst = (const int*)d_in[16];
    const int* et  = (const int*)d_in[17];
    float* out = (float*)d_out;

    const int NB_SCAN = (N_ENT + 511) / 512;   // 98

    k_zero<<<(N_ENT + 255) / 256, 256>>>();
    k_count<<<(N_EDGE + 255) / 256, 256>>>(dst);
    k_scan1<<<NB_SCAN, 512>>>();
    k_proj<<<dim3((N_ENT + 63) / 64, N_REL / 8), 256>>>(ent, WR);
    k_scan2<<<1, 32>>>(NB_SCAN);
    k_scan3<<<(N_ENT + 511) / 512, 512>>>();
    k_scatter<<<(N_EDGE + 255) / 256, 256>>>(src, dst, et);
    k_att<<<(N_EDGE / 4 + 7) / 8, 256>>>(rel);
    k_softmax<<<(N_ENT + 7) / 8, 256>>>();
    k_layer<0><<<(N_ENT + 7) / 8, 256>>>(ent, W1_0, b1_0, W2_0, b2_0, out);
    k_layer<1><<<(N_ENT + 7) / 8, 256>>>(ent, W1_1, b1_1, W2_1, b2_1, out);
    k_layer<2><<<(N_ENT + 7) / 8, 256>>>(ent, W1_2, b1_2, W2_2, b2_2, out);
}

// round 16
// speedup vs baseline: 1.0055x; 1.0048x over previous
#include <cuda_runtime.h>
#include <cuda_bf16.h>
#include <cuda_fp16.h>
#include <math.h>

#define N_ENT  50000
#define N_REL  16
#define N_EDGE 1000000
#define DOUT_TOTAL 176

// ---------------- scratch ----------------
__device__ __half g_projh[(size_t)N_REL * N_ENT * 64];  // 102.4 MB (fp16)
__device__ float g_att[N_EDGE];     // attention logits, CSR(dst)-sorted order
__device__ float g_a[N_EDGE];       // softmax-normalized coefs, CSR order
__device__ int   g_deg[N_ENT];
__device__ int   g_incl[N_ENT];
__device__ int   g_offs[N_ENT + 1];
__device__ int   g_cursor[N_ENT];
__device__ int   g_bsum[256];
__device__ int   g_srcs[N_EDGE];    // src, CSR order
__device__ int   g_dsts[N_EDGE];    // dst, CSR order
__device__ int   g_ets[N_EDGE];     // etype, CSR order
__device__ float g_h1[(size_t)N_ENT * 64];
__device__ float g_h2[(size_t)N_ENT * 32];

// packed fp32x2 FMA (Blackwell dual-fp32 pipe)
__device__ __forceinline__ float2 ffma2(float2 a, float2 b, float2 c) {
    float2 d;
    asm("fma.rn.f32x2 %0, %1, %2, %3;"
        : "=l"(reinterpret_cast<unsigned long long&>(d))
        : "l"(reinterpret_cast<const unsigned long long&>(a)),
          "l"(reinterpret_cast<const unsigned long long&>(b)),
          "l"(reinterpret_cast<const unsigned long long&>(c)));
    return d;
}

__device__ __forceinline__ unsigned f2tf32(float f) {
    unsigned u;
    asm("cvt.rna.tf32.f32 %0, %1;" : "=r"(u) : "f"(f));
    return u;
}

__device__ __forceinline__ float tanha(float x) {
    float y;
    asm("tanh.approx.f32 %0, %1;" : "=f"(y) : "f"(x));
    return y;
}

__device__ __forceinline__ void mma_tf32(float& d0, float& d1, float& d2, float& d3,
                                         unsigned a0, unsigned a1, unsigned a2, unsigned a3,
                                         unsigned b0, unsigned b1) {
    asm("mma.sync.aligned.m16n8k8.row.col.f32.tf32.tf32.f32 "
        "{%0,%1,%2,%3}, {%4,%5,%6,%7}, {%8,%9}, {%0,%1,%2,%3};"
        : "+f"(d0), "+f"(d1), "+f"(d2), "+f"(d3)
        : "r"(a0), "r"(a1), "r"(a2), "r"(a3), "r"(b0), "r"(b1));
}

// ---------------- init ----------------
__global__ __launch_bounds__(256) void k_zero() {
    int i = blockIdx.x * blockDim.x + threadIdx.x;
    if (i < N_ENT) { g_deg[i] = 0; g_cursor[i] = 0; }
}

// ---------------- proj[r,n,e] = sum_d ent[n,d] * W_R[r,d,e]  (tensor cores, fp16 out) ------
// Block: 256 thr (8 warps). Tile: 64 nodes x 64 cols, 8 relations per block.
// Warp: 32 nodes x 16 cols. mt loop innermost -> 2 interleaved mma chains (ILP 2).
__global__ __launch_bounds__(256, 2) void k_proj(const float* __restrict__ ent,
                                                 const float* __restrict__ WR) {
    __shared__ unsigned entS[64 * 68];   // [node][k], pitch 68 -> conflict-free frags
    __shared__ unsigned WT[64 * 68];     // [n][k] transposed, pitch 68

    const int tid  = threadIdx.x;
    const int lane = tid & 31;
    const int w    = tid >> 5;
    const int n0   = blockIdx.x * 64;

    // fill entS (tf32-converted)
    for (int i = tid; i < 1024; i += 256) {
        int row = i >> 4, q = i & 15;
        int n = n0 + row;
        float4 v = (n < N_ENT)
            ? reinterpret_cast<const float4*>(ent + (size_t)n * 64)[q]
            : make_float4(0.f, 0.f, 0.f, 0.f);
        entS[row * 68 + 4 * q + 0] = f2tf32(v.x);
        entS[row * 68 + 4 * q + 1] = f2tf32(v.y);
        entS[row * 68 + 4 * q + 2] = f2tf32(v.z);
        entS[row * 68 + 4 * q + 3] = f2tf32(v.w);
    }
    __syncthreads();

    const int grp  = lane >> 2;       // 0..7
    const int tq   = lane & 3;        // 0..3
    const int mb   = (w >> 2) * 32;   // node base within tile (0 or 32)
    const int nb   = (w & 3) * 16;    // col base within tile (0,16,32,48)

    // cache A fragments (2 m-tiles x 8 k-tiles), reused for all 8 relations
    unsigned a[2][8][4];
#pragma unroll
    for (int mt = 0; mt < 2; mt++) {
        int rowA = mb + mt * 16 + grp;
#pragma unroll
        for (int kt = 0; kt < 8; kt++) {
            int col = kt * 8 + tq;
            a[mt][kt][0] = entS[rowA * 68 + col];
            a[mt][kt][1] = entS[(rowA + 8) * 68 + col];
            a[mt][kt][2] = entS[rowA * 68 + col + 4];
            a[mt][kt][3] = entS[(rowA + 8) * 68 + col + 4];
        }
    }

    for (int rr = 0; rr < 8; rr++) {
        const int r = blockIdx.y * 8 + rr;
        __syncthreads();   // protect WT from previous iteration's reads
        const float* W = WR + (size_t)r * 4096;
        for (int i = tid; i < 4096; i += 256) {
            int k = i >> 6, n = i & 63;
            WT[n * 68 + k] = f2tf32(W[i]);
        }
        __syncthreads();

        __half* outb = g_projh + ((size_t)r * N_ENT + n0) * 64;
#pragma unroll
        for (int nt = 0; nt < 2; nt++) {
            unsigned b[8][2];
            const unsigned* wb = &WT[(nb + nt * 8 + grp) * 68];
#pragma unroll
            for (int kt = 0; kt < 8; kt++) {
                b[kt][0] = wb[kt * 8 + tq];
                b[kt][1] = wb[kt * 8 + tq + 4];
            }
            float d[2][4];
#pragma unroll
            for (int mt = 0; mt < 2; mt++)
                d[mt][0] = d[mt][1] = d[mt][2] = d[mt][3] = 0.f;
            // kt outer, mt inner: two independent mma chains interleave (ILP 2)
#pragma unroll
            for (int kt = 0; kt < 8; kt++) {
#pragma unroll
                for (int mt = 0; mt < 2; mt++)
                    mma_tf32(d[mt][0], d[mt][1], d[mt][2], d[mt][3],
                             a[mt][kt][0], a[mt][kt][1], a[mt][kt][2], a[mt][kt][3],
                             b[kt][0], b[kt][1]);
            }
            int colb = nb + nt * 8 + 2 * tq;
#pragma unroll
            for (int mt = 0; mt < 2; mt++) {
                int node0 = mb + mt * 16 + grp;
                int node1 = node0 + 8;
                if (n0 + node0 < N_ENT)
                    *reinterpret_cast<__half2*>(&outb[(size_t)node0 * 64 + colb]) =
                        __floats2half2_rn(d[mt][0], d[mt][1]);
                if (n0 + node1 < N_ENT)
                    *reinterpret_cast<__half2*>(&outb[(size_t)node1 * 64 + colb]) =
                        __floats2half2_rn(d[mt][2], d[mt][3]);
            }
        }
    }
}

// ---------------- CSR build ----------------
__global__ __launch_bounds__(256) void k_count(const int* __restrict__ dst) {
    int e = blockIdx.x * blockDim.x + threadIdx.x;
    if (e < N_EDGE) atomicAdd(&g_deg[dst[e]], 1);
}

__global__ __launch_bounds__(512) void k_scan1() {
    __shared__ int sm[512];
    int i = blockIdx.x * 512 + threadIdx.x;
    int v = (i < N_ENT) ? g_deg[i] : 0;
    sm[threadIdx.x] = v;
    __syncthreads();
    for (int off = 1; off < 512; off <<= 1) {
        int t = (threadIdx.x >= off) ? sm[threadIdx.x - off] : 0;
        __syncthreads();
        sm[threadIdx.x] += t;
        __syncthreads();
    }
    if (i < N_ENT) g_incl[i] = sm[threadIdx.x];
    if (threadIdx.x == 511) g_bsum[blockIdx.x] = sm[511];
}

__global__ void k_scan2(int nb) {
    if (blockIdx.x == 0 && threadIdx.x == 0) {
        int run = 0;
        for (int b = 0; b < nb; b++) { int t = g_bsum[b]; g_bsum[b] = run; run += t; }
    }
}

__global__ __launch_bounds__(512) void k_scan3() {
    int i = blockIdx.x * blockDim.x + threadIdx.x;
    if (i < N_ENT) g_offs[i] = g_incl[i] - g_deg[i] + g_bsum[i / 512];
    if (i == 0) g_offs[N_ENT] = N_EDGE;
}

__global__ __launch_bounds__(256) void k_scatter(const int* __restrict__ src,
                                                 const int* __restrict__ dst,
                                                 const int* __restrict__ et) {
    int e = blockIdx.x * blockDim.x + threadIdx.x;
    if (e < N_EDGE) {
        int d = dst[e];
        int pos = g_offs[d] + atomicAdd(&g_cursor[d], 1);
        g_srcs[pos] = src[e];
        g_dsts[pos] = d;
        g_ets[pos]  = et[e];
    }
}

// ---------------- attention logits: 8 lanes per edge, 4 edges per warp ----------------
// fp16 proj row = 128B = 8 lanes x LDG.128; tanh.approx on MUFU; 3-shfl reduce.
__global__ __launch_bounds__(256) void k_att(const float* __restrict__ rel) {
    int w = (blockIdx.x * blockDim.x + threadIdx.x) >> 5;
    int lane = threadIdx.x & 31;
    int base = w * 4;                 // N_EDGE % 4 == 0
    if (base >= N_EDGE) return;

    int g   = lane >> 3;              // edge slot 0..3
    int sub = lane & 7;               // 16B chunk within row

    int mv = 0;
    int el = base + (lane & 3);
    if (lane < 4)                      mv = g_srcs[el];
    else if (lane >= 8 && lane < 12)   mv = g_dsts[el];
    else if (lane >= 16 && lane < 20)  mv = g_ets[el];

    int s = __shfl_sync(0xffffffffu, mv, g);
    int d = __shfl_sync(0xffffffffu, mv, 8 + g);
    int r = __shfl_sync(0xffffffffu, mv, 16 + g);

    const uint4* pt = reinterpret_cast<const uint4*>(g_projh + ((size_t)r * N_ENT + s) * 64);
    const uint4* ph = reinterpret_cast<const uint4*>(g_projh + ((size_t)r * N_ENT + d) * 64);
    uint4 tv = pt[sub];
    uint4 hv = ph[sub];
    const float4* pr = reinterpret_cast<const float4*>(rel + (size_t)r * 64);
    float4 r0 = pr[2 * sub], r1 = pr[2 * sub + 1];

    const __half2* t2p = reinterpret_cast<const __half2*>(&tv);
    const __half2* h2p = reinterpret_cast<const __half2*>(&hv);
    float rc[8] = {r0.x, r0.y, r0.z, r0.w, r1.x, r1.y, r1.z, r1.w};

    float p = 0.0f;
#pragma unroll
    for (int q = 0; q < 4; q++) {
        float2 t2 = __half22float2(t2p[q]);
        float2 h2 = __half22float2(h2p[q]);
        p += t2.x * tanha(h2.x + rc[2 * q]);
        p += t2.y * tanha(h2.y + rc[2 * q + 1]);
    }
    // reduce within 8-lane group
    p += __shfl_xor_sync(0xffffffffu, p, 1);
    p += __shfl_xor_sync(0xffffffffu, p, 2);
    p += __shfl_xor_sync(0xffffffffu, p, 4);
    if (sub == 0) g_att[base + g] = p;
}

// ---------------- edge softmax by dst (warp per node, all-sequential IO) ----------------
__global__ __launch_bounds__(256) void k_softmax() {
    int n = blockIdx.x * (blockDim.x >> 5) + (threadIdx.x >> 5);
    int lane = threadIdx.x & 31;
    if (n >= N_ENT) return;
    int beg = g_offs[n], end = g_offs[n + 1];
    if (beg == end) return;
    float m = -3.4e38f;
    for (int p = beg + lane; p < end; p += 32) m = fmaxf(m, g_att[p]);
#pragma unroll
    for (int o = 16; o; o >>= 1) m = fmaxf(m, __shfl_xor_sync(0xffffffffu, m, o));
    float s = 0.0f;
    for (int p = beg + lane; p < end; p += 32) {
        float e = expf(g_att[p] - m);
        g_a[p] = e;
        s += e;
    }
#pragma unroll
    for (int o = 16; o; o >>= 1) s += __shfl_xor_sync(0xffffffffu, s, o);
    float inv = 1.0f / s;
    for (int p = beg + lane; p < end; p += 32) g_a[p] *= inv;
}

// ---------------- fused layer: agg + bi-interaction + l2norm + output ----------------
template <int L>
__global__ __launch_bounds__(256) void k_layer(const float* __restrict__ ent,
                                               const float* __restrict__ W1,
                                               const float* __restrict__ b1,
                                               const float* __restrict__ W2,
                                               const float* __restrict__ b2,
                                               float* __restrict__ out) {
    constexpr int DIN  = (L == 0) ? 64 : (L == 1) ? 64 : 32;
    constexpr int DOUT = (L == 0) ? 64 : (L == 1) ? 32 : 16;
    constexpr int CB   = (L == 0) ? 64 : (L == 1) ? 128 : 160;
    constexpr int V    = DIN / 32;
    constexpr int OV   = (DOUT + 31) / 32;
    const float* hin = (L == 0) ? ent : (L == 1) ? g_h1 : g_h2;
    float* hout      = (L == 0) ? g_h1 : (L == 1) ? g_h2 : nullptr;

    __shared__ float2 Wint[DIN * DOUT];
    __shared__ float2 bint[DOUT];
    for (int i = threadIdx.x; i < DIN * DOUT; i += blockDim.x)
        Wint[i] = make_float2(W1[i], W2[i]);
    if (threadIdx.x < DOUT)
        bint[threadIdx.x] = make_float2(b1[threadIdx.x], b2[threadIdx.x]);
    __syncthreads();

    int lane = threadIdx.x & 31;
    int n = blockIdx.x * (blockDim.x >> 5) + (threadIdx.x >> 5);
    if (n >= N_ENT) return;

    float hv[V], nv[V];
#pragma unroll
    for (int v = 0; v < V; v++) {
        hv[v] = hin[(size_t)n * DIN + lane + 32 * v];
        nv[v] = 0.0f;
    }
    int beg = g_offs[n], end = g_offs[n + 1];
    for (int p = beg; p < end; p++) {
        float c = g_a[p];
        const float* hs = hin + (size_t)g_srcs[p] * DIN;
#pragma unroll
        for (int v = 0; v < V; v++) nv[v] += c * hs[lane + 32 * v];
    }

    float sv1[V], sv2[V];
#pragma unroll
    for (int v = 0; v < V; v++) { sv1[v] = hv[v] + nv[v]; sv2[v] = hv[v] * nv[v]; }

    float2 acc[OV];
#pragma unroll
    for (int o = 0; o < OV; o++) acc[o] = make_float2(0.0f, 0.0f);
#pragma unroll
    for (int i = 0; i < DIN; i++) {
        float x1 = __shfl_sync(0xffffffffu, sv1[i >> 5], i & 31);
        float x2 = __shfl_sync(0xffffffffu, sv2[i >> 5], i & 31);
        float2 xp = make_float2(x1, x2);
#pragma unroll
        for (int o = 0; o < OV; o++) {
            int j = lane + 32 * o;
            if (j < DOUT) acc[o] = ffma2(xp, Wint[i * DOUT + j], acc[o]);
        }
    }

    float y[OV];
    float ss = 0.0f;
#pragma unroll
    for (int o = 0; o < OV; o++) {
        int j = lane + 32 * o;
        if (j < DOUT) {
            float y1 = acc[o].x + bint[j].x; y1 = (y1 > 0.0f) ? y1 : 0.01f * y1;
            float y2 = acc[o].y + bint[j].y; y2 = (y2 > 0.0f) ? y2 : 0.01f * y2;
            y[o] = y1 + y2;
            ss += y[o] * y[o];
        }
    }
#pragma unroll
    for (int o = 16; o; o >>= 1) ss += __shfl_xor_sync(0xffffffffu, ss, o);
    float inv = 1.0f / fmaxf(sqrtf(ss), 1e-12f);

#pragma unroll
    for (int o = 0; o < OV; o++) {
        int j = lane + 32 * o;
        if (j < DOUT) {
            if (hout) hout[(size_t)n * DOUT + j] = y[o];
            out[(size_t)n * DOUT_TOTAL + CB + j] = y[o] * inv;
        }
    }
    if (L == 0) {
#pragma unroll
        for (int v = 0; v < V; v++)
            out[(size_t)n * DOUT_TOTAL + lane + 32 * v] = hv[v];
    }
}

// ---------------- launch ----------------
extern "C" void kernel_launch(void* const* d_in, const int* in_sizes, int n_in,
                              void* d_out, int out_size) {
    const float* ent  = (const float*)d_in[0];
    const float* rel  = (const float*)d_in[1];
    const float* WR   = (const float*)d_in[2];
    const float* W1_0 = (const float*)d_in[3];
    const float* b1_0 = (const float*)d_in[4];
    const float* W2_0 = (const float*)d_in[5];
    const float* b2_0 = (const float*)d_in[6];
    const float* W1_1 = (const float*)d_in[7];
    const float* b1_1 = (const float*)d_in[8];
    const float* W2_1 = (const float*)d_in[9];
    const float* b2_1 = (const float*)d_in[10];
    const float* W1_2 = (const float*)d_in[11];
    const float* b1_2 = (const float*)d_in[12];
    const float* W2_2 = (const float*)d_in[13];
    const float* b2_2 = (const float*)d_in[14];
    const int* src = (const int*)d_in[15];
    const int* dst = (const int*)d_in[16];
    const int* et  = (const int*)d_in[17];
    float* out = (float*)d_out;

    const int NB_SCAN = (N_ENT + 511) / 512;   // 98

    k_zero<<<(N_ENT + 255) / 256, 256>>>();
    k_count<<<(N_EDGE + 255) / 256, 256>>>(dst);
    k_scan1<<<NB_SCAN, 512>>>();
    k_proj<<<dim3((N_ENT + 63) / 64, N_REL / 8), 256>>>(ent, WR);
    k_scan2<<<1, 32>>>(NB_SCAN);
    k_scan3<<<(N_ENT + 511) / 512, 512>>>();
    k_scatter<<<(N_EDGE + 255) / 256, 256>>>(src, dst, et);
    k_att<<<(N_EDGE / 4 + 7) / 8, 256>>>(rel);
    k_softmax<<<(N_ENT + 7) / 8, 256>>>();
    k_layer<0><<<(N_ENT + 7) / 8, 256>>>(ent, W1_0, b1_0, W2_0, b2_0, out);
    k_layer<1><<<(N_ENT + 7) / 8, 256>>>(ent, W1_1, b1_1, W2_1, b2_1, out);
    k_layer<2><<<(N_ENT + 7) / 8, 256>>>(ent, W1_2, b1_2, W2_2, b2_2, out);
}